// round 14
// baseline (speedup 1.0000x reference)
#include <cuda_runtime.h>
#include <cuda_fp16.h>
#include <cstdint>
#include <cstddef>

#define INNER 31999
#define VOCAB 32000
#define DEPTH 18
#define NROWS 64          // B*T
#define KDIM  512
#define MT    128         // nodes per block tile
#define KC    64          // fp16 K elems per A chunk (=128B per row)
#define NCHUNK (KDIM / KC)       // 8
#define B_BYTES 65536            // 64 rows * 1024B (full K, fp16)
#define A_ST    16384            // 128 rows * 128B per stage
#define SMEM_TOTAL (B_BYTES + 2 * A_ST)   // 98304

// Log-prob table: [2*node + side][row], fp16. side 0 = log sigma, side 1 = log(1-sigma).
__device__ __half g_L[(size_t)2 * VOCAB * NROWS];

// ---------------- helpers ----------------
__device__ __forceinline__ uint32_t smem_u32(const void* p) {
    return (uint32_t)__cvta_generic_to_shared(p);
}
__device__ __forceinline__ void ldsm4(uint32_t& r0, uint32_t& r1, uint32_t& r2, uint32_t& r3,
                                      uint32_t addr) {
    asm volatile("ldmatrix.sync.aligned.m8n8.x4.shared.b16 {%0,%1,%2,%3}, [%4];"
                 : "=r"(r0), "=r"(r1), "=r"(r2), "=r"(r3) : "r"(addr));
}
__device__ __forceinline__ void mma_f16(float* c, const uint32_t* a, const uint32_t* b) {
    asm volatile(
        "mma.sync.aligned.m16n8k16.row.col.f32.f16.f16.f32 "
        "{%0,%1,%2,%3}, {%4,%5,%6,%7}, {%8,%9}, {%0,%1,%2,%3};"
        : "+f"(c[0]), "+f"(c[1]), "+f"(c[2]), "+f"(c[3])
        : "r"(a[0]), "r"(a[1]), "r"(a[2]), "r"(a[3]), "r"(b[0]), "r"(b[1]));
}
__device__ __forceinline__ void sts64(uint32_t off, __half2 p0, __half2 p1) {
    asm volatile("st.shared.v2.b32 [%0], {%1, %2};"
                 :: "r"(off), "r"(*(uint32_t*)&p0), "r"(*(uint32_t*)&p1));
}

// ---------------------------------------------------------------------------
// Kernel 1 (r9 config, best measured): C[128 nodes, 64 rows] per block.
// fp16 m16n8k16 mma (fp32 acc). att fp32->fp16 once per block into K-resident
// smem B tile; A (W) streams via 2-stage reg-staged ring. 256 thr, 8 warps
// (4M x 2N), warp tile 32M x 32N, occ 2. Softplus epilogue + smem transpose.
// ---------------------------------------------------------------------------
__global__ __launch_bounds__(256, 2) void hs_gemm_kernel(
    const float* __restrict__ att, const float* __restrict__ W)
{
    extern __shared__ char smem[];
    const uint32_t sb = smem_u32(smem);          // B at sb, A stages at sb+B_BYTES

    const int tid   = threadIdx.x;
    const int lane  = tid & 31;
    const int warp  = tid >> 5;
    const int wm    = warp & 3;        // warp M index (rows wm*32..+31)
    const int wn    = warp >> 2;       // warp N index (cols wn*32..+31)
    const int nbase = blockIdx.x * MT;
    const int gid   = lane >> 2;
    const int tig   = lane & 3;

    // -------- B prologue: att [64x512] fp32 -> fp16 smem, swizzled --------
#pragma unroll
    for (int i = 0; i < 32; i++) {
        int u = tid + i * 256;
        int row = u >> 7, f4 = u & 127;
        float4 v = *reinterpret_cast<const float4*>(att + (size_t)row * KDIM + f4 * 4);
        uint32_t unit = (uint32_t)((f4 >> 1) ^ (row & 7));
        uint32_t off  = sb + (uint32_t)(row * 1024) + unit * 16 + (uint32_t)(f4 & 1) * 8;
        sts64(off, __floats2half2_rn(v.x, v.y), __floats2half2_rn(v.z, v.w));
    }

    // -------- A register staging: 8 float4 per thread per chunk --------
    float4 ra[8];
    auto ldg_stage = [&](int t) {
#pragma unroll
        for (int i = 0; i < 8; i++) {            // 128 rows x 16 float4 = 2048
            int u = tid + i * 256;
            int row = u >> 4, f4 = u & 15;
            int wr = nbase + row;
            if (wr < INNER)
                ra[i] = *reinterpret_cast<const float4*>(W + (size_t)wr * KDIM + t * KC + f4 * 4);
            else
                ra[i] = make_float4(0.f, 0.f, 0.f, 0.f);
        }
    };
    auto sts_A = [&](int buf) {
        const uint32_t base = sb + B_BYTES + (uint32_t)buf * A_ST;
#pragma unroll
        for (int i = 0; i < 8; i++) {
            int u = tid + i * 256;
            int row = u >> 4, f4 = u & 15;
            uint32_t unit = (uint32_t)((f4 >> 1) ^ (row & 7));
            uint32_t off  = base + (uint32_t)(row * 128) + unit * 16 + (uint32_t)(f4 & 1) * 8;
            sts64(off, __floats2half2_rn(ra[i].x, ra[i].y), __floats2half2_rn(ra[i].z, ra[i].w));
        }
    };

    // -------- ldmatrix per-lane address precompute --------
    const int li = lane >> 3;
    const int lr = lane & 7;
    const uint32_t kh = (uint32_t)(li >> 1);     // k 16B-half select
    uint32_t aBase[2], aX[2];
#pragma unroll
    for (int mt = 0; mt < 2; mt++) {
        int row = wm * 32 + mt * 16 + lr + ((li & 1) << 3);
        aBase[mt] = sb + B_BYTES + (uint32_t)(row * 128);
        aX[mt]    = (uint32_t)(row & 7);
    }
    uint32_t bBase[2], bX[2];
#pragma unroll
    for (int q = 0; q < 2; q++) {
        int row = wn * 32 + q * 16 + lr + ((li & 1) << 3);
        bBase[q] = sb + (uint32_t)(row * 1024);
        bX[q]    = (uint32_t)(row & 7);
    }

    float acc[2][4][4];
#pragma unroll
    for (int mt = 0; mt < 2; mt++)
#pragma unroll
        for (int f = 0; f < 4; f++)
#pragma unroll
            for (int c = 0; c < 4; c++) acc[mt][f][c] = 0.0f;

    // -------- prologue: A stage 0 in smem, stage 1 in regs --------
    ldg_stage(0);
    sts_A(0);
    ldg_stage(1);
    __syncthreads();                             // B tile + A stage 0 visible

    for (int t = 0; t < NCHUNK; t++) {
        if (t + 1 < NCHUNK) sts_A((t + 1) & 1);
        if (t + 2 < NCHUNK) ldg_stage(t + 2);

        const uint32_t Ab = (uint32_t)(t & 1) * A_ST;
#pragma unroll
        for (int ks = 0; ks < 4; ks++) {         // 4 x k16 per chunk
            uint32_t a[2][4];
#pragma unroll
            for (int mt = 0; mt < 2; mt++)
                ldsm4(a[mt][0], a[mt][1], a[mt][2], a[mt][3],
                      aBase[mt] + Ab + ((((uint32_t)(ks * 2) + kh) ^ aX[mt]) << 4));
            uint32_t b[4][2];
            const uint32_t ksg2 = (uint32_t)(t * 8 + ks * 2);
#pragma unroll
            for (int q = 0; q < 2; q++) {
                uint32_t r0, r1, r2, r3;
                ldsm4(r0, r1, r2, r3, bBase[q] + (((ksg2 + kh) ^ bX[q]) << 4));
                b[q * 2][0] = r0;     b[q * 2][1] = r2;
                b[q * 2 + 1][0] = r1; b[q * 2 + 1][1] = r3;
            }
#pragma unroll
            for (int mt = 0; mt < 2; mt++)
#pragma unroll
                for (int f = 0; f < 4; f++)
                    mma_f16(acc[mt][f], a[mt], b[f]);
        }
        __syncthreads();
    }

    // -------- epilogue: softplus -> fp16, smem transpose (swizzled), flat copy --------
#pragma unroll
    for (int mt = 0; mt < 2; mt++) {
#pragma unroll
        for (int m8 = 0; m8 < 2; m8++) {
            const int nl = wm * 32 + mt * 16 + m8 * 8 + gid;     // local node 0..127
            const uint32_t swz = (uint32_t)((nl & 7) << 4);
#pragma unroll
            for (int f = 0; f < 4; f++) {
                float lp[2], ln[2];
#pragma unroll
                for (int u = 0; u < 2; u++) {
                    float h = acc[mt][f][m8 * 2 + u];
                    float l = __logf(1.0f + __expf(-fabsf(h)));
                    lp[u] = fmaxf(fminf(h, 0.0f) - l, -20.7232658f);   // log sigma
                    ln[u] = fmaxf(-fmaxf(h, 0.0f) - l, -20.7232658f);  // log(1-sigma)
                }
                const uint32_t col = (uint32_t)(wn * 64 + f * 16 + tig * 4) ^ swz;
                *reinterpret_cast<__half2*>(smem + (2 * nl)     * 128 + col) = __floats2half2_rn(lp[0], lp[1]);
                *reinterpret_cast<__half2*>(smem + (2 * nl + 1) * 128 + col) = __floats2half2_rn(ln[0], ln[1]);
            }
        }
    }
    __syncthreads();

    char* gdst = reinterpret_cast<char*>(&g_L[(size_t)(2 * nbase) * NROWS]);
#pragma unroll
    for (int i = 0; i < 8; i++) {
        int u = tid + i * 256;               // 16B unit, 0..2047
        int s = u >> 3, j = u & 7;
        uint32_t soff = (uint32_t)(s * 128 + ((j ^ ((s >> 1) & 7)) << 4));
        uint4 v = *reinterpret_cast<const uint4*>(smem + soff);
        *reinterpret_cast<uint4*>(gdst + (size_t)u * 16) = v;
    }
}

// ---------------------------------------------------------------------------
// Kernel 2: depth-split gather. 16 words per block, 256 threads, grid 2000.
// Thread = (word, sub-chunk, depth-half): 9 batched LDG.128 each (half the
// serial chain of r10), fp16 tree reduce, halves combined via smem planes.
// ---------------------------------------------------------------------------
#define GWPB 16
__global__ __launch_bounds__(256) void hs_gather_kernel(
    const int* __restrict__ pidx, const float* __restrict__ psign,
    float* __restrict__ out)
{
    __shared__ uint16_t sci[GWPB * DEPTH];          // 288 packed child indices
    __shared__ float tr[2][NROWS][GWPB + 1];        // [half][row][word]

    const int tid   = threadIdx.x;
    const int wbase = blockIdx.x * GWPB;

    for (int j = tid; j < GWPB * DEPTH; j += 256) {
        int gj = wbase * DEPTH + j;
        sci[j] = (uint16_t)(2 * pidx[gj] + (psign[gj] < 0.0f ? 1 : 0));
    }
    __syncthreads();

    const int w    = tid >> 4;                      // word 0..15
    const int sub  = (tid >> 1) & 7;                // 16B chunk -> rows 8*sub..+7
    const int half = tid & 1;                       // depth half: 0 -> d0..8, 1 -> d9..17
    const int dbase = half * 9;

    // 9 independent LDG.128 in one batch
    uint4 v[9];
#pragma unroll
    for (int i = 0; i < 9; i++) {
        int ci = sci[w * DEPTH + dbase + i];
        v[i] = __ldg(reinterpret_cast<const uint4*>(&g_L[(size_t)ci * NROWS]) + sub);
    }

    // fp16 tree reduce 9 -> 1 per component, then cvt to fp32
    float acc[8];
#pragma unroll
    for (int c = 0; c < 4; c++) {
        const uint32_t* pv = reinterpret_cast<const uint32_t*>(v);
        __half2 p0 = __hadd2(*(const __half2*)&pv[0 * 4 + c], *(const __half2*)&pv[1 * 4 + c]);
        __half2 p1 = __hadd2(*(const __half2*)&pv[2 * 4 + c], *(const __half2*)&pv[3 * 4 + c]);
        __half2 p2 = __hadd2(*(const __half2*)&pv[4 * 4 + c], *(const __half2*)&pv[5 * 4 + c]);
        __half2 p3 = __hadd2(*(const __half2*)&pv[6 * 4 + c], *(const __half2*)&pv[7 * 4 + c]);
        __half2 s  = __hadd2(__hadd2(__hadd2(p0, p1), __hadd2(p2, p3)),
                             *(const __half2*)&pv[8 * 4 + c]);
        float2 f   = __half22float2(s);
        acc[2 * c]     = f.x;
        acc[2 * c + 1] = f.y;
    }

#pragma unroll
    for (int r = 0; r < 8; r++)
        tr[half][8 * sub + r][w] = acc[r];
    __syncthreads();

    // 64 rows x 16 words = 256 float4; 1 per thread. Combine halves here.
    {
        int row = tid >> 2;
        int q   = (tid & 3) * 4;
        float4 o;
        o.x = tr[0][row][q]     + tr[1][row][q];
        o.y = tr[0][row][q + 1] + tr[1][row][q + 1];
        o.z = tr[0][row][q + 2] + tr[1][row][q + 2];
        o.w = tr[0][row][q + 3] + tr[1][row][q + 3];
        *reinterpret_cast<float4*>(out + (size_t)row * VOCAB + wbase + q) = o;
    }
}

extern "C" void kernel_launch(void* const* d_in, const int* in_sizes, int n_in,
                              void* d_out, int out_size)
{
    (void)in_sizes; (void)n_in; (void)out_size;
    const float* att   = (const float*)d_in[0];
    const float* W     = (const float*)d_in[1];
    const int*   pidx  = (const int*)d_in[2];
    const float* psign = (const float*)d_in[3];
    float* out = (float*)d_out;

    cudaFuncSetAttribute(hs_gemm_kernel, cudaFuncAttributeMaxDynamicSharedMemorySize, SMEM_TOTAL);
    hs_gemm_kernel<<<(INNER + MT - 1) / MT, 256, SMEM_TOTAL>>>(att, W);
    hs_gather_kernel<<<VOCAB / GWPB, 256>>>(pidx, psign, out);
}

// round 15
// speedup vs baseline: 1.0909x; 1.0909x over previous
#include <cuda_runtime.h>
#include <cuda_fp16.h>
#include <cstdint>
#include <cstddef>

#define INNER 31999
#define VOCAB 32000
#define DEPTH 18
#define NROWS 64          // B*T
#define KDIM  512
#define MT    128         // nodes per block tile
#define KC    64          // fp16 K elems per A chunk (=128B per row)
#define NCHUNK (KDIM / KC)       // 8
#define B_BYTES 65536            // 64 rows * 1024B (full K, fp16)
#define A_ST    16384            // 128 rows * 128B per stage
#define SMEM_TOTAL (B_BYTES + 2 * A_ST)   // 98304

// Log-prob table: [2*node + side][row], fp16. side 0 = log sigma, side 1 = log(1-sigma).
__device__ __half g_L[(size_t)2 * VOCAB * NROWS];

// ---------------- helpers ----------------
__device__ __forceinline__ uint32_t smem_u32(const void* p) {
    return (uint32_t)__cvta_generic_to_shared(p);
}
__device__ __forceinline__ void ldsm4(uint32_t& r0, uint32_t& r1, uint32_t& r2, uint32_t& r3,
                                      uint32_t addr) {
    asm volatile("ldmatrix.sync.aligned.m8n8.x4.shared.b16 {%0,%1,%2,%3}, [%4];"
                 : "=r"(r0), "=r"(r1), "=r"(r2), "=r"(r3) : "r"(addr));
}
__device__ __forceinline__ void mma_f16(float* c, const uint32_t* a, const uint32_t* b) {
    asm volatile(
        "mma.sync.aligned.m16n8k16.row.col.f32.f16.f16.f32 "
        "{%0,%1,%2,%3}, {%4,%5,%6,%7}, {%8,%9}, {%0,%1,%2,%3};"
        : "+f"(c[0]), "+f"(c[1]), "+f"(c[2]), "+f"(c[3])
        : "r"(a[0]), "r"(a[1]), "r"(a[2]), "r"(a[3]), "r"(b[0]), "r"(b[1]));
}
__device__ __forceinline__ void sts64(uint32_t off, __half2 p0, __half2 p1) {
    asm volatile("st.shared.v2.b32 [%0], {%1, %2};"
                 :: "r"(off), "r"(*(uint32_t*)&p0), "r"(*(uint32_t*)&p1));
}

// ---------------------------------------------------------------------------
// Kernel 1 (r9 config + L1-bypass W stream): C[128 nodes, 64 rows] per block.
// fp16 m16n8k16 mma (fp32 acc). att fp32->fp16 once per block into K-resident
// smem B tile; A (W) streams via 2-stage reg-staged ring with __ldcg (L2-only
// -- W is touched once, L1 allocation is pure L1TEX overhead). 256 thr,
// 8 warps (4M x 2N), warp tile 32M x 32N, occ 2. Softplus epilogue,
// smem transpose, __stcg g_L stores (consumed from L2, never via L1).
// ---------------------------------------------------------------------------
__global__ __launch_bounds__(256, 2) void hs_gemm_kernel(
    const float* __restrict__ att, const float* __restrict__ W)
{
    extern __shared__ char smem[];
    const uint32_t sb = smem_u32(smem);          // B at sb, A stages at sb+B_BYTES

    const int tid   = threadIdx.x;
    const int lane  = tid & 31;
    const int warp  = tid >> 5;
    const int wm    = warp & 3;        // warp M index (rows wm*32..+31)
    const int wn    = warp >> 2;       // warp N index (cols wn*32..+31)
    const int nbase = blockIdx.x * MT;
    const int gid   = lane >> 2;
    const int tig   = lane & 3;

    // -------- B prologue: att [64x512] fp32 -> fp16 smem, swizzled --------
#pragma unroll
    for (int i = 0; i < 32; i++) {
        int u = tid + i * 256;
        int row = u >> 7, f4 = u & 127;
        float4 v = __ldcg(reinterpret_cast<const float4*>(att + (size_t)row * KDIM + f4 * 4));
        uint32_t unit = (uint32_t)((f4 >> 1) ^ (row & 7));
        uint32_t off  = sb + (uint32_t)(row * 1024) + unit * 16 + (uint32_t)(f4 & 1) * 8;
        sts64(off, __floats2half2_rn(v.x, v.y), __floats2half2_rn(v.z, v.w));
    }

    // -------- A register staging: 8 float4 per thread per chunk --------
    float4 ra[8];
    auto ldg_stage = [&](int t) {
#pragma unroll
        for (int i = 0; i < 8; i++) {            // 128 rows x 16 float4 = 2048
            int u = tid + i * 256;
            int row = u >> 4, f4 = u & 15;
            int wr = nbase + row;
            if (wr < INNER)
                ra[i] = __ldcg(reinterpret_cast<const float4*>(
                            W + (size_t)wr * KDIM + t * KC + f4 * 4));
            else
                ra[i] = make_float4(0.f, 0.f, 0.f, 0.f);
        }
    };
    auto sts_A = [&](int buf) {
        const uint32_t base = sb + B_BYTES + (uint32_t)buf * A_ST;
#pragma unroll
        for (int i = 0; i < 8; i++) {
            int u = tid + i * 256;
            int row = u >> 4, f4 = u & 15;
            uint32_t unit = (uint32_t)((f4 >> 1) ^ (row & 7));
            uint32_t off  = base + (uint32_t)(row * 128) + unit * 16 + (uint32_t)(f4 & 1) * 8;
            sts64(off, __floats2half2_rn(ra[i].x, ra[i].y), __floats2half2_rn(ra[i].z, ra[i].w));
        }
    };

    // -------- ldmatrix per-lane address precompute --------
    const int li = lane >> 3;
    const int lr = lane & 7;
    const uint32_t kh = (uint32_t)(li >> 1);     // k 16B-half select
    uint32_t aBase[2], aX[2];
#pragma unroll
    for (int mt = 0; mt < 2; mt++) {
        int row = wm * 32 + mt * 16 + lr + ((li & 1) << 3);
        aBase[mt] = sb + B_BYTES + (uint32_t)(row * 128);
        aX[mt]    = (uint32_t)(row & 7);
    }
    uint32_t bBase[2], bX[2];
#pragma unroll
    for (int q = 0; q < 2; q++) {
        int row = wn * 32 + q * 16 + lr + ((li & 1) << 3);
        bBase[q] = sb + (uint32_t)(row * 1024);
        bX[q]    = (uint32_t)(row & 7);
    }

    float acc[2][4][4];
#pragma unroll
    for (int mt = 0; mt < 2; mt++)
#pragma unroll
        for (int f = 0; f < 4; f++)
#pragma unroll
            for (int c = 0; c < 4; c++) acc[mt][f][c] = 0.0f;

    // -------- prologue: A stage 0 in smem, stage 1 in regs --------
    ldg_stage(0);
    sts_A(0);
    ldg_stage(1);
    __syncthreads();                             // B tile + A stage 0 visible

    for (int t = 0; t < NCHUNK; t++) {
        if (t + 1 < NCHUNK) sts_A((t + 1) & 1);
        if (t + 2 < NCHUNK) ldg_stage(t + 2);

        const uint32_t Ab = (uint32_t)(t & 1) * A_ST;
#pragma unroll
        for (int ks = 0; ks < 4; ks++) {         // 4 x k16 per chunk
            uint32_t a[2][4];
#pragma unroll
            for (int mt = 0; mt < 2; mt++)
                ldsm4(a[mt][0], a[mt][1], a[mt][2], a[mt][3],
                      aBase[mt] + Ab + ((((uint32_t)(ks * 2) + kh) ^ aX[mt]) << 4));
            uint32_t b[4][2];
            const uint32_t ksg2 = (uint32_t)(t * 8 + ks * 2);
#pragma unroll
            for (int q = 0; q < 2; q++) {
                uint32_t r0, r1, r2, r3;
                ldsm4(r0, r1, r2, r3, bBase[q] + (((ksg2 + kh) ^ bX[q]) << 4));
                b[q * 2][0] = r0;     b[q * 2][1] = r2;
                b[q * 2 + 1][0] = r1; b[q * 2 + 1][1] = r3;
            }
#pragma unroll
            for (int mt = 0; mt < 2; mt++)
#pragma unroll
                for (int f = 0; f < 4; f++)
                    mma_f16(acc[mt][f], a[mt], b[f]);
        }
        __syncthreads();
    }

    // -------- epilogue: softplus -> fp16, smem transpose (swizzled), flat copy --------
#pragma unroll
    for (int mt = 0; mt < 2; mt++) {
#pragma unroll
        for (int m8 = 0; m8 < 2; m8++) {
            const int nl = wm * 32 + mt * 16 + m8 * 8 + gid;     // local node 0..127
            const uint32_t swz = (uint32_t)((nl & 7) << 4);
#pragma unroll
            for (int f = 0; f < 4; f++) {
                float lp[2], ln[2];
#pragma unroll
                for (int u = 0; u < 2; u++) {
                    float h = acc[mt][f][m8 * 2 + u];
                    float l = __logf(1.0f + __expf(-fabsf(h)));
                    lp[u] = fmaxf(fminf(h, 0.0f) - l, -20.7232658f);   // log sigma
                    ln[u] = fmaxf(-fmaxf(h, 0.0f) - l, -20.7232658f);  // log(1-sigma)
                }
                const uint32_t col = (uint32_t)(wn * 64 + f * 16 + tig * 4) ^ swz;
                *reinterpret_cast<__half2*>(smem + (2 * nl)     * 128 + col) = __floats2half2_rn(lp[0], lp[1]);
                *reinterpret_cast<__half2*>(smem + (2 * nl + 1) * 128 + col) = __floats2half2_rn(ln[0], ln[1]);
            }
        }
    }
    __syncthreads();

    char* gdst = reinterpret_cast<char*>(&g_L[(size_t)(2 * nbase) * NROWS]);
#pragma unroll
    for (int i = 0; i < 8; i++) {
        int u = tid + i * 256;               // 16B unit, 0..2047
        int s = u >> 3, j = u & 7;
        uint32_t soff = (uint32_t)(s * 128 + ((j ^ ((s >> 1) & 7)) << 4));
        uint4 v = *reinterpret_cast<const uint4*>(smem + soff);
        __stcg(reinterpret_cast<uint4*>(gdst + (size_t)u * 16), v);
    }
}

// ---------------------------------------------------------------------------
// Kernel 2: 32 words per block (8 warps x 4 words), 256 threads, grid 1000.
// LDG.128 table reads via __ldcg (L2-only, NO L1 allocate -- the table is a
// random-access 8MB working set with ~zero L1 reuse; L1 fills were the
// bottleneck at 52% L1TEX). 3 groups of 6 loads, HADD2 tree, fp32 accumulate.
// ---------------------------------------------------------------------------
#define GWPB 32
__global__ __launch_bounds__(256) void hs_gather_kernel(
    const int* __restrict__ pidx, const float* __restrict__ psign,
    float* __restrict__ out)
{
    __shared__ uint16_t sci[GWPB * DEPTH];      // 576 packed child indices
    __shared__ float tr[NROWS * (GWPB + 1)];    // [row][word], pad 33

    const int tid   = threadIdx.x;
    const int lane  = tid & 31;
    const int warp  = tid >> 5;
    const int g     = lane >> 3;                 // word-in-warp 0..3
    const int sub   = lane & 7;                  // 16B sub-chunk -> rows 8*sub..+7
    const int wbase = blockIdx.x * GWPB;

    for (int j = tid; j < GWPB * DEPTH; j += 256) {
        int gj = wbase * DEPTH + j;
        sci[j] = (uint16_t)(2 * pidx[gj] + (psign[gj] < 0.0f ? 1 : 0));
    }
    __syncthreads();

    const int wloc = warp * 4 + g;               // word within block 0..31

    float acc[8] = {0.f, 0.f, 0.f, 0.f, 0.f, 0.f, 0.f, 0.f};
#pragma unroll
    for (int grp = 0; grp < 3; grp++) {
        uint4 v[6];
#pragma unroll
        for (int d = 0; d < 6; d++) {
            int ci = sci[wloc * DEPTH + grp * 6 + d];
            v[d] = __ldcg(reinterpret_cast<const uint4*>(&g_L[(size_t)ci * NROWS]) + sub);
        }
        // tree reduce 6 -> 1 (per 32-bit component = pair of rows)
#pragma unroll
        for (int c = 0; c < 4; c++) {
            const uint32_t* pv = reinterpret_cast<const uint32_t*>(v);
            __half2 p0 = __hadd2(*(const __half2*)&pv[0 * 4 + c], *(const __half2*)&pv[1 * 4 + c]);
            __half2 p1 = __hadd2(*(const __half2*)&pv[2 * 4 + c], *(const __half2*)&pv[3 * 4 + c]);
            __half2 p2 = __hadd2(*(const __half2*)&pv[4 * 4 + c], *(const __half2*)&pv[5 * 4 + c]);
            __half2 s  = __hadd2(__hadd2(p0, p1), p2);
            float2 f   = __half22float2(s);
            acc[2 * c]     += f.x;
            acc[2 * c + 1] += f.y;
        }
    }

    // rows 8*sub + r, word wloc
#pragma unroll
    for (int r = 0; r < 8; r++)
        tr[(8 * sub + r) * (GWPB + 1) + wloc] = acc[r];
    __syncthreads();

    // 64 rows x 32 words = 2048 floats = 512 float4; 2 per thread
#pragma unroll
    for (int i = 0; i < 2; i++) {
        int u   = tid + i * 256;
        int row = u >> 3;
        int q   = (u & 7) * 4;
        float4 o = make_float4(tr[row * (GWPB + 1) + q],     tr[row * (GWPB + 1) + q + 1],
                               tr[row * (GWPB + 1) + q + 2], tr[row * (GWPB + 1) + q + 3]);
        *reinterpret_cast<float4*>(out + (size_t)row * VOCAB + wbase + q) = o;
    }
}

extern "C" void kernel_launch(void* const* d_in, const int* in_sizes, int n_in,
                              void* d_out, int out_size)
{
    (void)in_sizes; (void)n_in; (void)out_size;
    const float* att   = (const float*)d_in[0];
    const float* W     = (const float*)d_in[1];
    const int*   pidx  = (const int*)d_in[2];
    const float* psign = (const float*)d_in[3];
    float* out = (float*)d_out;

    cudaFuncSetAttribute(hs_gemm_kernel, cudaFuncAttributeMaxDynamicSharedMemorySize, SMEM_TOTAL);
    hs_gemm_kernel<<<(INNER + MT - 1) / MT, 256, SMEM_TOTAL>>>(att, W);
    hs_gather_kernel<<<VOCAB / GWPB, 256>>>(pidx, psign, out);
}